// round 15
// baseline (speedup 1.0000x reference)
#include <cuda_runtime.h>
#include <cstdint>

// ============================ helpers ============================
__device__ __forceinline__ uint32_t smem_u32(const void* p) {
    uint32_t a;
    asm("{ .reg .u64 t; cvta.to.shared.u64 t, %1; cvt.u32.u64 %0, t; }" : "=r"(a) : "l"(p));
    return a;
}
__device__ __forceinline__ unsigned short f2bf(float f) {
    unsigned short r; asm("cvt.rn.bf16.f32 %0, %1;" : "=h"(r) : "f"(f)); return r;
}
__device__ __forceinline__ float bf2f(unsigned short u) {
    return __uint_as_float(((uint32_t)u) << 16);
}
__device__ __forceinline__ uint32_t packbf(float a, float b) {
    uint32_t r; asm("cvt.rn.bf16x2.f32 %0, %1, %2;" : "=r"(r) : "f"(b), "f"(a)); return r;
}

#define LDM4(r, addr) \
    asm volatile("ldmatrix.sync.aligned.m8n8.x4.shared.b16 {%0,%1,%2,%3}, [%4];" \
        : "=r"((r)[0]), "=r"((r)[1]), "=r"((r)[2]), "=r"((r)[3]) : "r"(addr))

#define LDM4T(r, addr) \
    asm volatile("ldmatrix.sync.aligned.m8n8.x4.trans.shared.b16 {%0,%1,%2,%3}, [%4];" \
        : "=r"((r)[0]), "=r"((r)[1]), "=r"((r)[2]), "=r"((r)[3]) : "r"(addr))

#define MMA_BF16(c, a, b0, b1) \
    asm volatile("mma.sync.aligned.m16n8k16.row.col.f32.bf16.bf16.f32 " \
        "{%0,%1,%2,%3}, {%4,%5,%6,%7}, {%8,%9}, {%0,%1,%2,%3};" \
        : "+f"((c)[0]), "+f"((c)[1]), "+f"((c)[2]), "+f"((c)[3]) \
        : "r"((a)[0]), "r"((a)[1]), "r"((a)[2]), "r"((a)[3]), "r"(b0), "r"(b1))

#define CP_COMMIT() asm volatile("cp.async.commit_group;" ::: "memory")
#define CP_WAIT0()  asm volatile("cp.async.wait_group 0;" ::: "memory")
#define CP_WAIT1()  asm volatile("cp.async.wait_group 1;" ::: "memory")
#define CP_WAIT2()  asm volatile("cp.async.wait_group 2;" ::: "memory")
__device__ __forceinline__ void cp16(uint32_t dst_smem, const void* src) {
    asm volatile("cp.async.cg.shared.global [%0], [%1], 16;"
        :: "r"(dst_smem), "l"(__cvta_generic_to_global(src)) : "memory");
}

// ============================ constants ============================
constexpr int WN  = 49;
constexpr int D   = 128;
constexpr float SCALE = 0.17677669529663687f;
constexpr int NT = 256;                // threads per CTA

// prepacked weights: 8 chunks (6 qkv + 2 wout), each [hi 18432 | lo 18432]
__device__ unsigned char g_wpk[8][36864];

// per-CTA smem (one window):
// XH(x-hi/attn-hi) 0 | XL(x-lo->Q) 17408 | KB(k->attn-lo) 34816 |
// VH 52224 | VL 69632 | W ring 87040 (18432) | bias 105472
constexpr int S_XL   = 17408;
constexpr int S_KB   = 34816;
constexpr int S_VH   = 52224;
constexpr int S_VL   = 69632;
constexpr int F_W    = 87040;
constexpr int F_BIAS = 105472;
constexpr int F_TOTAL = 108176;

// ======================= weight prepack kernel =======================
__global__ void prepack_w(const float* __restrict__ wqkv,
                          const float* __restrict__ wout)
{
    int idx = blockIdx.x * 256 + threadIdx.x;
    if (idx < 128 * 384) {
        int k = idx / 384, n = idx - (idx / 384) * 384;
        float v = wqkv[idx];
        unsigned short h = f2bf(v), l = f2bf(v - bf2f(h));
        int c = n >> 6, nn = n & 63;
        *(unsigned short*)(g_wpk[c] + k * 144 + nn * 2) = h;
        *(unsigned short*)(g_wpk[c] + 18432 + k * 144 + nn * 2) = l;
    } else if (idx < 128 * 384 + 128 * 128) {
        int i2 = idx - 128 * 384;
        int k = i2 >> 7, n = i2 & 127;
        float v = wout[i2];
        unsigned short h = f2bf(v), l = f2bf(v - bf2f(h));
        int c = 6 + (n >> 6), nn = n & 63;
        *(unsigned short*)(g_wpk[c] + k * 144 + nn * 2) = h;
        *(unsigned short*)(g_wpk[c] + 18432 + k * 144 + nn * 2) = l;
    }
}

// ============ slab issuers (one 16-k-row slab per kt) ============
// v / out slabs: 9216 B (2 chunks x hi/lo); ring2 slots {0,9216}
__device__ __forceinline__ void issue_vo(uint32_t sb, int slot, int kt, int t,
                                         int cbase) {
    for (int i = t; i < 576; i += NT) {
        int b = i / 144, ii = i - b * 144;
        cp16(sb + F_W + slot * 9216 + b * 2304 + ii * 16,
             g_wpk[cbase + (b >> 1)] + (b & 1) * 18432 + kt * 2304 + ii * 16);
    }
    CP_COMMIT();
}
// q / k slabs: 4608 B (2 chunks, hi only); ring4 slots {0,4608,9216,13824}
__device__ __forceinline__ void issue_qk(uint32_t sb, int slot, int kt, int t,
                                         int cbase) {
    for (int i = t; i < 288; i += NT) {
        int b = i / 144, ii = i - b * 144;
        cp16(sb + F_W + slot * 4608 + b * 2304 + ii * 16,
             g_wpk[cbase + b] + kt * 2304 + ii * 16);
    }
    CP_COMMIT();
}

// ====== fused kernel: 1 window / CTA, 2 CTAs / SM, 8 warps, 32x32 tiles ======
__global__ __launch_bounds__(NT, 2)
void fused1(const float* __restrict__ x, const float* __restrict__ btab,
            float* __restrict__ out)
{
    extern __shared__ char smc[];
    const uint32_t sb = smem_u32(smc);
    const int t = threadIdx.x;
    const int w = t >> 5, lane = t & 31;
    const int wn = w >> 1;          // n 32-col tile (0..3)
    const int wp = w & 1;           // m 32-row pair (0..1)
    const int lrow = lane & 15, lhalf = lane >> 4;
    const int qrow = lane >> 2, qt2 = (lane & 3) << 1;
    const size_t win = blockIdx.x;
    float* bias_s = (float*)(smc + F_BIAS);

    // bootstrap v-slab ring
    issue_vo(sb, 0, 0, t, 4);
    issue_vo(sb, 1, 1, t, 4);

    // zero ONLY x pad rows 49..63 of XH/XL (Q/K/V pads become zero via GEMM)
    {
        uint4 z4 = make_uint4(0u, 0u, 0u, 0u);
        for (int i = t; i < 510; i += NT) {
            int buf = (i >= 255);
            int k = i - buf * 255;
            *((uint4*)(smc + buf * S_XL + 49 * 272) + k) = z4;
        }
    }
    for (int i = t; i < 676; i += NT) bias_s[i] = btab[i];

    // stage x -> split bf16 (XH/XL)
    {
        const float* xw = x + win * (size_t)(WN * D);
        for (int idx4 = t; idx4 < 1568; idx4 += NT) {
            int r  = idx4 >> 5;
            int c4 = (idx4 & 31) << 2;
            float4 v = *(const float4*)(xw + r * D + c4);
            float vv[4] = {v.x, v.y, v.z, v.w};
            unsigned short hh[4], ll[4];
#pragma unroll
            for (int e = 0; e < 4; e++) {
                hh[e] = f2bf(vv[e]); ll[e] = f2bf(vv[e] - bf2f(hh[e]));
            }
            int off = r * 272 + c4 * 2;
            *(uint2*)(smc + off) = make_uint2(
                (uint32_t)hh[0] | ((uint32_t)hh[1] << 16),
                (uint32_t)hh[2] | ((uint32_t)hh[3] << 16));
            *(uint2*)(smc + S_XL + off) = make_uint2(
                (uint32_t)ll[0] | ((uint32_t)ll[1] << 16),
                (uint32_t)ll[2] | ((uint32_t)ll[3] << 16));
        }
    }

    // ================= stage V (3-pass split), ring2 =================
    {
        float acc[2][4][4];
#pragma unroll
        for (int mt = 0; mt < 2; mt++)
#pragma unroll
            for (int j = 0; j < 4; j++)
#pragma unroll
                for (int e = 0; e < 4; e++) acc[mt][j][e] = 0.f;

#pragma unroll 1
        for (int kt = 0; kt < 8; kt++) {
            if (kt < 7) CP_WAIT1(); else CP_WAIT0();
            __syncthreads();                       // slab kt ready

            uint32_t ah[2][4], al[2][4], bh[2][4], bl[2][4];
#pragma unroll
            for (int mt = 0; mt < 2; mt++) {
                uint32_t aoff = (uint32_t)((wp * 32 + mt * 16 + lrow) * 272
                                           + kt * 32 + lhalf * 16);
                LDM4(ah[mt], sb + aoff);
                LDM4(al[mt], sb + S_XL + aoff);
            }
            uint32_t pbase = sb + F_W + (kt & 1) * 9216 + (wn >> 1) * 4608;
#pragma unroll
            for (int nt = 0; nt < 2; nt++) {
                uint32_t boff = (uint32_t)(lrow * 144
                                + ((wn & 1) * 32 + nt * 16) * 2 + lhalf * 16);
                LDM4T(bh[nt], pbase + boff);
                LDM4T(bl[nt], pbase + 2304 + boff);
            }
#pragma unroll
            for (int mt = 0; mt < 2; mt++)
#pragma unroll
                for (int j = 0; j < 4; j++)
                    MMA_BF16(acc[mt][j], ah[mt], bh[j >> 1][2 * (j & 1)],
                             bh[j >> 1][2 * (j & 1) + 1]);
#pragma unroll
            for (int mt = 0; mt < 2; mt++)
#pragma unroll
                for (int j = 0; j < 4; j++)
                    MMA_BF16(acc[mt][j], ah[mt], bl[j >> 1][2 * (j & 1)],
                             bl[j >> 1][2 * (j & 1) + 1]);
#pragma unroll
            for (int mt = 0; mt < 2; mt++)
#pragma unroll
                for (int j = 0; j < 4; j++)
                    MMA_BF16(acc[mt][j], al[mt], bh[j >> 1][2 * (j & 1)],
                             bh[j >> 1][2 * (j & 1) + 1]);

            __syncthreads();                       // slot drained
            if (kt < 6) issue_vo(sb, kt & 1, kt + 2, t, 4);
        }
        // pre-issue q slabs (ring4 slots 0,1,2)
        issue_qk(sb, 0, 0, t, 0);
        issue_qk(sb, 1, 1, t, 0);
        issue_qk(sb, 2, 2, t, 0);

        // epilogue: split v -> VH/VL
#pragma unroll
        for (int mt = 0; mt < 2; mt++) {
            const int r0 = wp * 32 + mt * 16 + qrow, r1 = r0 + 8;
#pragma unroll
            for (int j = 0; j < 4; j++) {
                int cb = (wn * 32 + j * 8 + qt2) * 2;
                {
                    int off = r0 * 272 + cb;
                    uint32_t hp = packbf(acc[mt][j][0], acc[mt][j][1]);
                    float ra = acc[mt][j][0] - __uint_as_float(hp << 16);
                    float rb = acc[mt][j][1] - __uint_as_float(hp & 0xFFFF0000u);
                    *(uint32_t*)(smc + S_VH + off) = hp;
                    *(uint32_t*)(smc + S_VL + off) = packbf(ra, rb);
                }
                {
                    int off = r1 * 272 + cb;
                    uint32_t hp = packbf(acc[mt][j][2], acc[mt][j][3]);
                    float ra = acc[mt][j][2] - __uint_as_float(hp << 16);
                    float rb = acc[mt][j][3] - __uint_as_float(hp & 0xFFFF0000u);
                    *(uint32_t*)(smc + S_VH + off) = hp;
                    *(uint32_t*)(smc + S_VL + off) = packbf(ra, rb);
                }
            }
        }
    }

    // ============ stages Q (ss=0) and K (ss=1): single-pass, ring4 ============
#pragma unroll 1
    for (int ss = 0; ss < 2; ss++) {
        float acc[2][4][4];
#pragma unroll
        for (int mt = 0; mt < 2; mt++)
#pragma unroll
            for (int j = 0; j < 4; j++)
#pragma unroll
                for (int e = 0; e < 4; e++) acc[mt][j][e] = 0.f;

#pragma unroll 1
        for (int kt = 0; kt < 8; kt++) {
            if (kt < 6) CP_WAIT2(); else if (kt == 6) CP_WAIT1(); else CP_WAIT0();
            __syncthreads();                       // slab kt ready; kt-1 drained
            if (kt < 5) issue_qk(sb, (kt + 3) & 3, kt + 3, t, ss == 0 ? 0 : 2);

            uint32_t ah[2][4], bh[2][4];
#pragma unroll
            for (int mt = 0; mt < 2; mt++) {
                uint32_t aoff = (uint32_t)((wp * 32 + mt * 16 + lrow) * 272
                                           + kt * 32 + lhalf * 16);
                LDM4(ah[mt], sb + aoff);           // x-hi only
            }
            uint32_t pbase = sb + F_W + (kt & 3) * 4608 + (wn >> 1) * 2304;
#pragma unroll
            for (int nt = 0; nt < 2; nt++) {
                uint32_t boff = (uint32_t)(lrow * 144
                                + ((wn & 1) * 32 + nt * 16) * 2 + lhalf * 16);
                LDM4T(bh[nt], pbase + boff);
            }
#pragma unroll
            for (int mt = 0; mt < 2; mt++)
#pragma unroll
                for (int j = 0; j < 4; j++)
                    MMA_BF16(acc[mt][j], ah[mt], bh[j >> 1][2 * (j & 1)],
                             bh[j >> 1][2 * (j & 1) + 1]);
        }
        if (ss == 0) {       // pre-issue k slabs: slots 0,1,2
            issue_qk(sb, 0, 0, t, 2);
            issue_qk(sb, 1, 1, t, 2);
            issue_qk(sb, 2, 2, t, 2);
        }
        // epilogue: q -> XL, k -> KB (single bf16)
        const int base = (ss == 0) ? S_XL : S_KB;
#pragma unroll
        for (int mt = 0; mt < 2; mt++) {
            const int r0 = wp * 32 + mt * 16 + qrow, r1 = r0 + 8;
#pragma unroll
            for (int j = 0; j < 4; j++) {
                int cb = (wn * 32 + j * 8 + qt2) * 2;
                *(uint32_t*)(smc + base + r0 * 272 + cb) =
                    packbf(acc[mt][j][0], acc[mt][j][1]);
                *(uint32_t*)(smc + base + r1 * 272 + cb) =
                    packbf(acc[mt][j][2], acc[mt][j][3]);
            }
        }
    }
    __syncthreads();                 // Q/K/V visible
    // pre-issue out-proj slabs (ring2)
    issue_vo(sb, 0, 0, t, 6);
    issue_vo(sb, 1, 1, t, 6);

    // ============== attention: 2 tasks per warp, register-buffered ==============
    {
        float ocA[2][4][4];
        float invA[2][2];

#pragma unroll
        for (int it = 0; it < 2; it++) {
            const int task = w + it * 8;
            const int h  = task >> 2;
            const int i0 = (task & 3) << 4;
            const uint32_t QB = sb + S_XL;
            const uint32_t KBa = sb + S_KB;
            const uint32_t VB = sb + S_VH;

            float sc[7][4];
#pragma unroll
            for (int nt = 0; nt < 7; nt++)
#pragma unroll
                for (int e = 0; e < 4; e++) sc[nt][e] = 0.f;

            // S = q k^T, single-pass
#pragma unroll
            for (int kt = 0; kt < 2; kt++) {
                uint32_t ah[4], bh[4][4];
                uint32_t coff = (uint32_t)((h * 32 + kt * 16) * 2 + lhalf * 16);
                LDM4(ah, QB + (uint32_t)((i0 + lrow) * 272) + coff);
#pragma unroll
                for (int g = 0; g < 4; g++)
                    LDM4(bh[g], KBa + (uint32_t)((g * 16 + lrow) * 272) + coff);
#pragma unroll
                for (int nt = 0; nt < 7; nt++)
                    MMA_BF16(sc[nt], ah, bh[nt >> 1][nt & 1],
                             bh[nt >> 1][2 + (nt & 1)]);
            }

            // softmax in fragments (unnormalized)
            const int r0 = i0 + qrow, r1 = r0 + 8;
            const int gi0 = r0 / 7, gj0 = r0 - 7 * gi0;
            const int gi1 = r1 / 7, gj1 = r1 - 7 * gi1;
            float rs0 = 0.f, rs1 = 0.f;
#pragma unroll
            for (int nt = 0; nt < 7; nt++) {
#pragma unroll
                for (int e = 0; e < 4; e++) {
                    int j = nt * 8 + qt2 + (e & 1);
                    int r = (e < 2) ? r0 : r1;
                    float ev = 0.f;
                    if (r < 49 && j < 49) {
                        int gj2 = j / 7;
                        int gjj = j - 7 * gj2;
                        int gi = (e < 2) ? gi0 : gi1;
                        int gj = (e < 2) ? gj0 : gj1;
                        int bidx = ((gi - gj2 + 6) * 13 + (gj - gjj + 6)) * 4 + h;
                        ev = __expf(sc[nt][e] * SCALE + bias_s[bidx]);
                    }
                    sc[nt][e] = ev;
                    if (e < 2) rs0 += ev; else rs1 += ev;
                }
            }
            rs0 += __shfl_xor_sync(0xFFFFFFFFu, rs0, 1);
            rs0 += __shfl_xor_sync(0xFFFFFFFFu, rs0, 2);
            rs1 += __shfl_xor_sync(0xFFFFFFFFu, rs1, 1);
            rs1 += __shfl_xor_sync(0xFFFFFFFFu, rs1, 2);
            invA[it][0] = (r0 < 49) ? 1.f / rs0 : 0.f;
            invA[it][1] = (r1 < 49) ? 1.f / rs1 : 0.f;

            // O = P V
#pragma unroll
            for (int nt = 0; nt < 4; nt++)
#pragma unroll
                for (int e = 0; e < 4; e++) ocA[it][nt][e] = 0.f;

#pragma unroll
            for (int kt2 = 0; kt2 < 4; kt2++) {
                const int lo = 2 * kt2, hi = lo + 1;
                float pe[8];
                pe[0] = sc[lo][0]; pe[1] = sc[lo][1];
                pe[2] = sc[lo][2]; pe[3] = sc[lo][3];
                if (hi < 7) {
                    pe[4] = sc[hi][0]; pe[5] = sc[hi][1];
                    pe[6] = sc[hi][2]; pe[7] = sc[hi][3];
                } else {
                    pe[4] = pe[5] = pe[6] = pe[7] = 0.f;
                }
                uint32_t ph[4], pl[4];
#pragma unroll
                for (int g = 0; g < 4; g++) {
                    float a = pe[2 * g], b = pe[2 * g + 1];
                    uint32_t hp = packbf(a, b);
                    float ra = a - __uint_as_float(hp << 16);
                    float rb = b - __uint_as_float(hp & 0xFFFF0000u);
                    ph[g] = hp;
                    pl[g] = packbf(ra, rb);
                }
                uint32_t vh[2][4], vl[2][4];
#pragma unroll
                for (int g = 0; g < 2; g++) {
                    uint32_t voff = (uint32_t)((kt2 * 16 + lrow) * 272
                                               + h * 64 + g * 32 + lhalf * 16);
                    LDM4T(vh[g], VB + voff);
                    LDM4T(vl[g], VB + 17408 + voff);
                }
#pragma unroll
                for (int nt = 0; nt < 4; nt++)
                    MMA_BF16(ocA[it][nt], ph, vh[nt >> 1][2 * (nt & 1)],
                             vh[nt >> 1][2 * (nt & 1) + 1]);
#pragma unroll
                for (int nt = 0; nt < 4; nt++)
                    MMA_BF16(ocA[it][nt], ph, vl[nt >> 1][2 * (nt & 1)],
                             vl[nt >> 1][2 * (nt & 1) + 1]);
#pragma unroll
                for (int nt = 0; nt < 4; nt++)
                    MMA_BF16(ocA[it][nt], pl, vh[nt >> 1][2 * (nt & 1)],
                             vh[nt >> 1][2 * (nt & 1) + 1]);
            }
        }

        __syncthreads();   // all Q/K/V reads done before attn-out overwrites

        // write both tasks: hi -> XH, lo -> KB (split bf16)
#pragma unroll
        for (int it = 0; it < 2; it++) {
            const int task = w + it * 8;
            const int h  = task >> 2;
            const int i0 = (task & 3) << 4;
            const int r0 = i0 + qrow, r1 = r0 + 8;
            const float inv0 = invA[it][0], inv1 = invA[it][1];
#pragma unroll
            for (int nt = 0; nt < 4; nt++) {
                int cb = (h * 32 + nt * 8 + qt2) * 2;
                if (r0 < 49) {
                    float a = ocA[it][nt][0] * inv0, b = ocA[it][nt][1] * inv0;
                    uint32_t hp = packbf(a, b);
                    float ra = a - __uint_as_float(hp << 16);
                    float rb = b - __uint_as_float(hp & 0xFFFF0000u);
                    int off = r0 * 272 + cb;
                    *(uint32_t*)(smc + off) = hp;
                    *(uint32_t*)(smc + S_KB + off) = packbf(ra, rb);
                }
                if (r1 < 49) {
                    float a = ocA[it][nt][2] * inv1, b = ocA[it][nt][3] * inv1;
                    uint32_t hp = packbf(a, b);
                    float ra = a - __uint_as_float(hp << 16);
                    float rb = b - __uint_as_float(hp & 0xFFFF0000u);
                    int off = r1 * 272 + cb;
                    *(uint32_t*)(smc + off) = hp;
                    *(uint32_t*)(smc + S_KB + off) = packbf(ra, rb);
                }
            }
        }
    }

    // ================= out-proj (3-pass split), ring2 =================
    {
        float acc[2][4][4];
#pragma unroll
        for (int mt = 0; mt < 2; mt++)
#pragma unroll
            for (int j = 0; j < 4; j++)
#pragma unroll
                for (int e = 0; e < 4; e++) acc[mt][j][e] = 0.f;

#pragma unroll 1
        for (int kt = 0; kt < 8; kt++) {
            if (kt < 7) CP_WAIT1(); else CP_WAIT0();
            __syncthreads();                   // slab ready + attn-out visible

            uint32_t ah[2][4], al[2][4], bh[2][4], bl[2][4];
#pragma unroll
            for (int mt = 0; mt < 2; mt++) {
                uint32_t aoff = (uint32_t)((wp * 32 + mt * 16 + lrow) * 272
                                           + kt * 32 + lhalf * 16);
                LDM4(ah[mt], sb + aoff);               // attn-out hi (XH)
                LDM4(al[mt], sb + S_KB + aoff);        // attn-out lo (KB)
            }
            uint32_t pbase = sb + F_W + (kt & 1) * 9216 + (wn >> 1) * 4608;
#pragma unroll
            for (int nt = 0; nt < 2; nt++) {
                uint32_t boff = (uint32_t)(lrow * 144
                                + ((wn & 1) * 32 + nt * 16) * 2 + lhalf * 16);
                LDM4T(bh[nt], pbase + boff);
                LDM4T(bl[nt], pbase + 2304 + boff);
            }
#pragma unroll
            for (int mt = 0; mt < 2; mt++)
#pragma unroll
                for (int j = 0; j < 4; j++)
                    MMA_BF16(acc[mt][j], ah[mt], bh[j >> 1][2 * (j & 1)],
                             bh[j >> 1][2 * (j & 1) + 1]);
#pragma unroll
            for (int mt = 0; mt < 2; mt++)
#pragma unroll
                for (int j = 0; j < 4; j++)
                    MMA_BF16(acc[mt][j], ah[mt], bl[j >> 1][2 * (j & 1)],
                             bl[j >> 1][2 * (j & 1) + 1]);
#pragma unroll
            for (int mt = 0; mt < 2; mt++)
#pragma unroll
                for (int j = 0; j < 4; j++)
                    MMA_BF16(acc[mt][j], al[mt], bh[j >> 1][2 * (j & 1)],
                             bh[j >> 1][2 * (j & 1) + 1]);

            __syncthreads();                   // slot drained
            if (kt < 6) issue_vo(sb, kt & 1, kt + 2, t, 6);
        }

#pragma unroll
        for (int mt = 0; mt < 2; mt++) {
            const int r0 = wp * 32 + mt * 16 + qrow, r1 = r0 + 8;
#pragma unroll
            for (int j = 0; j < 4; j++) {
                int col = wn * 32 + j * 8 + qt2;
                if (r0 < 49)
                    *(float2*)(out + (win * WN + r0) * (size_t)D + col) =
                        make_float2(acc[mt][j][0], acc[mt][j][1]);
                if (r1 < 49)
                    *(float2*)(out + (win * WN + r1) * (size_t)D + col) =
                        make_float2(acc[mt][j][2], acc[mt][j][3]);
            }
        }
    }
}

// ============================== launcher ==============================
extern "C" void kernel_launch(void* const* d_in, const int* in_sizes, int n_in,
                              void* d_out, int out_size) {
    const float* x    = (const float*)d_in[0];
    const float* wqkv = (const float*)d_in[1];
    const float* wout = (const float*)d_in[2];
    const float* btab = (const float*)d_in[3];
    float* out = (float*)d_out;

    const int n_win = in_sizes[0] / (WN * D);

    cudaFuncSetAttribute(fused1,
                         cudaFuncAttributeMaxDynamicSharedMemorySize, F_TOTAL);

    prepack_w<<<256, 256>>>(wqkv, wout);
    fused1<<<n_win, NT, F_TOTAL>>>(x, btab, out);
}

// round 16
// speedup vs baseline: 1.0539x; 1.0539x over previous
#include <cuda_runtime.h>
#include <cstdint>

// ============================ helpers ============================
__device__ __forceinline__ uint32_t smem_u32(const void* p) {
    uint32_t a;
    asm("{ .reg .u64 t; cvta.to.shared.u64 t, %1; cvt.u32.u64 %0, t; }" : "=r"(a) : "l"(p));
    return a;
}
__device__ __forceinline__ unsigned short f2bf(float f) {
    unsigned short r; asm("cvt.rn.bf16.f32 %0, %1;" : "=h"(r) : "f"(f)); return r;
}
__device__ __forceinline__ float bf2f(unsigned short u) {
    return __uint_as_float(((uint32_t)u) << 16);
}
__device__ __forceinline__ uint32_t packbf(float a, float b) {
    uint32_t r; asm("cvt.rn.bf16x2.f32 %0, %1, %2;" : "=r"(r) : "f"(b), "f"(a)); return r;
}

#define LDM4(r, addr) \
    asm volatile("ldmatrix.sync.aligned.m8n8.x4.shared.b16 {%0,%1,%2,%3}, [%4];" \
        : "=r"((r)[0]), "=r"((r)[1]), "=r"((r)[2]), "=r"((r)[3]) : "r"(addr))

#define LDM4T(r, addr) \
    asm volatile("ldmatrix.sync.aligned.m8n8.x4.trans.shared.b16 {%0,%1,%2,%3}, [%4];" \
        : "=r"((r)[0]), "=r"((r)[1]), "=r"((r)[2]), "=r"((r)[3]) : "r"(addr))

#define MMA_BF16(c, a, b0, b1) \
    asm volatile("mma.sync.aligned.m16n8k16.row.col.f32.bf16.bf16.f32 " \
        "{%0,%1,%2,%3}, {%4,%5,%6,%7}, {%8,%9}, {%0,%1,%2,%3};" \
        : "+f"((c)[0]), "+f"((c)[1]), "+f"((c)[2]), "+f"((c)[3]) \
        : "r"((a)[0]), "r"((a)[1]), "r"((a)[2]), "r"((a)[3]), "r"(b0), "r"(b1))

#define CP_COMMIT() asm volatile("cp.async.commit_group;" ::: "memory")
#define CP_WAIT0()  asm volatile("cp.async.wait_group 0;" ::: "memory")
#define CP_WAIT1()  asm volatile("cp.async.wait_group 1;" ::: "memory")
__device__ __forceinline__ void cp16(uint32_t dst_smem, const void* src) {
    asm volatile("cp.async.cg.shared.global [%0], [%1], 16;"
        :: "r"(dst_smem), "l"(__cvta_generic_to_global(src)) : "memory");
}

// ============================ constants ============================
constexpr int WN  = 49;
constexpr int D   = 128;
constexpr float SCALE = 0.17677669529663687f;

// prepacked weights: 8 chunks (6 qkv + 2 wout), each [hi 18432 | lo 18432]
// per half: k(0..127)*144 + n_local(0..63)*2
__device__ unsigned char g_wpk[8][36864];

// per-CTA smem (one window):
// XH(x-hi/attn-hi) 0 | XL(x-lo->Q) 17408 | KB(k->attn-lo) 34816 |
// VH 52224 | VL 69632 | W ring 87040 (18432) | bias 105472
constexpr int S_XL   = 17408;
constexpr int S_KB   = 34816;
constexpr int S_VH   = 52224;
constexpr int S_VL   = 69632;
constexpr int F_W    = 87040;
constexpr int F_BIAS = 105472;
constexpr int F_TOTAL = 108176;

// ======================= weight prepack kernel =======================
__global__ void prepack_w(const float* __restrict__ wqkv,
                          const float* __restrict__ wout)
{
    int idx = blockIdx.x * 256 + threadIdx.x;
    if (idx < 128 * 384) {
        int k = idx / 384, n = idx - (idx / 384) * 384;
        float v = wqkv[idx];
        unsigned short h = f2bf(v), l = f2bf(v - bf2f(h));
        int c = n >> 6, nn = n & 63;
        *(unsigned short*)(g_wpk[c] + k * 144 + nn * 2) = h;
        *(unsigned short*)(g_wpk[c] + 18432 + k * 144 + nn * 2) = l;
    } else if (idx < 128 * 384 + 128 * 128) {
        int i2 = idx - 128 * 384;
        int k = i2 >> 7, n = i2 & 127;
        float v = wout[i2];
        unsigned short h = f2bf(v), l = f2bf(v - bf2f(h));
        int c = 6 + (n >> 6), nn = n & 63;
        *(unsigned short*)(g_wpk[c] + k * 144 + nn * 2) = h;
        *(unsigned short*)(g_wpk[c] + 18432 + k * 144 + nn * 2) = l;
    }
}

// ============ slab issuers (one 16-k-row slab per kt) ============
// v / out slabs: 9216 B (2 chunks x hi/lo); ring2 slots {0,9216}
__device__ __forceinline__ void issue_vo(uint32_t sb, int slot, int kt, int t,
                                         int cbase) {
    for (int i = t; i < 576; i += 512) {
        int b = i / 144, ii = i - b * 144;
        cp16(sb + F_W + slot * 9216 + b * 2304 + ii * 16,
             g_wpk[cbase + (b >> 1)] + (b & 1) * 18432 + kt * 2304 + ii * 16);
    }
    CP_COMMIT();
}
// combined q+k slab: chunks 0..3 hi-halves, 9216 B; ring2
__device__ __forceinline__ void issue_qk2(uint32_t sb, int slot, int kt, int t) {
    for (int i = t; i < 576; i += 512) {
        int b = i / 144, ii = i - b * 144;
        cp16(sb + F_W + slot * 9216 + b * 2304 + ii * 16,
             g_wpk[b] + kt * 2304 + ii * 16);
    }
    CP_COMMIT();
}

// ================== fused kernel: 1 window / CTA, 2 CTAs / SM ==================
__global__ __launch_bounds__(512, 2)
void fused1(const float* __restrict__ x, const float* __restrict__ btab,
            float* __restrict__ out)
{
    extern __shared__ char smc[];
    const uint32_t sb = smem_u32(smc);
    const int t = threadIdx.x;
    const int w = t >> 5, lane = t & 31;
    const int wm = w & 3, wn = w >> 2;
    const int lrow = lane & 15, lhalf = lane >> 4;
    const int qrow = lane >> 2, qt2 = (lane & 3) << 1;
    const size_t win = blockIdx.x;
    float* bias_s = (float*)(smc + F_BIAS);

    // bootstrap v-slab ring
    issue_vo(sb, 0, 0, t, 4);
    issue_vo(sb, 1, 1, t, 4);

    // zero ONLY x pad rows 49..63 of XH/XL (Q/K/V pads become 0 via GEMM)
    {
        uint4 z4 = make_uint4(0u, 0u, 0u, 0u);
        for (int i = t; i < 510; i += 512) {
            int buf = (i >= 255);
            int k = i - buf * 255;
            *((uint4*)(smc + buf * S_XL + 49 * 272) + k) = z4;
        }
    }
    for (int i = t; i < 676; i += 512) bias_s[i] = btab[i];

    // stage x -> split bf16 (XH/XL)
    {
        const float* xw = x + win * (size_t)(WN * D);
        for (int idx4 = t; idx4 < 1568; idx4 += 512) {
            int r  = idx4 >> 5;
            int c4 = (idx4 & 31) << 2;
            float4 v = *(const float4*)(xw + r * D + c4);
            float vv[4] = {v.x, v.y, v.z, v.w};
            unsigned short hh[4], ll[4];
#pragma unroll
            for (int e = 0; e < 4; e++) {
                hh[e] = f2bf(vv[e]); ll[e] = f2bf(vv[e] - bf2f(hh[e]));
            }
            int off = r * 272 + c4 * 2;
            *(uint2*)(smc + off) = make_uint2(
                (uint32_t)hh[0] | ((uint32_t)hh[1] << 16),
                (uint32_t)hh[2] | ((uint32_t)hh[3] << 16));
            *(uint2*)(smc + S_XL + off) = make_uint2(
                (uint32_t)ll[0] | ((uint32_t)ll[1] << 16),
                (uint32_t)ll[2] | ((uint32_t)ll[3] << 16));
        }
    }

    // ================= stage V (3-pass split), ring2 =================
    {
        float acc[4][4];
#pragma unroll
        for (int j = 0; j < 4; j++)
#pragma unroll
            for (int e = 0; e < 4; e++) acc[j][e] = 0.f;

#pragma unroll 1
        for (int kt = 0; kt < 8; kt++) {
            if (kt < 7) CP_WAIT1(); else CP_WAIT0();
            __syncthreads();                       // slab kt ready

            uint32_t ah[4], al[4], bh[2][4], bl[2][4];
            uint32_t aoff = (uint32_t)((wm * 16 + lrow) * 272
                                       + kt * 32 + lhalf * 16);
            LDM4(ah, sb + aoff);
            LDM4(al, sb + S_XL + aoff);
            uint32_t pbase = sb + F_W + (kt & 1) * 9216 + (wn >> 1) * 4608;
#pragma unroll
            for (int nt = 0; nt < 2; nt++) {
                uint32_t boff = (uint32_t)(lrow * 144
                                + ((wn & 1) * 32 + nt * 16) * 2 + lhalf * 16);
                LDM4T(bh[nt], pbase + boff);
                LDM4T(bl[nt], pbase + 2304 + boff);
            }
#pragma unroll
            for (int j = 0; j < 4; j++)
                MMA_BF16(acc[j], ah, bh[j >> 1][2 * (j & 1)],
                         bh[j >> 1][2 * (j & 1) + 1]);
#pragma unroll
            for (int j = 0; j < 4; j++)
                MMA_BF16(acc[j], ah, bl[j >> 1][2 * (j & 1)],
                         bl[j >> 1][2 * (j & 1) + 1]);
#pragma unroll
            for (int j = 0; j < 4; j++)
                MMA_BF16(acc[j], al, bh[j >> 1][2 * (j & 1)],
                         bh[j >> 1][2 * (j & 1) + 1]);

            __syncthreads();                       // slot drained
            if (kt < 6) issue_vo(sb, kt & 1, kt + 2, t, 4);
        }
        // pre-issue combined q+k slabs (ring2 slots 0,1)
        issue_qk2(sb, 0, 0, t);
        issue_qk2(sb, 1, 1, t);

        // epilogue: split v -> VH/VL
        const int r0 = wm * 16 + qrow, r1 = r0 + 8;
#pragma unroll
        for (int j = 0; j < 4; j++) {
            int cb = (wn * 32 + j * 8 + qt2) * 2;
            {
                int off = r0 * 272 + cb;
                uint32_t hp = packbf(acc[j][0], acc[j][1]);
                float ra = acc[j][0] - __uint_as_float(hp << 16);
                float rb = acc[j][1] - __uint_as_float(hp & 0xFFFF0000u);
                *(uint32_t*)(smc + S_VH + off) = hp;
                *(uint32_t*)(smc + S_VL + off) = packbf(ra, rb);
            }
            {
                int off = r1 * 272 + cb;
                uint32_t hp = packbf(acc[j][2], acc[j][3]);
                float ra = acc[j][2] - __uint_as_float(hp << 16);
                float rb = acc[j][3] - __uint_as_float(hp & 0xFFFF0000u);
                *(uint32_t*)(smc + S_VH + off) = hp;
                *(uint32_t*)(smc + S_VL + off) = packbf(ra, rb);
            }
        }
    }

    // ============ merged Q+K stage: single-pass bf16, shared A, ring2 ============
    {
        float aq[4][4], ak[4][4];
#pragma unroll
        for (int j = 0; j < 4; j++)
#pragma unroll
            for (int e = 0; e < 4; e++) { aq[j][e] = 0.f; ak[j][e] = 0.f; }

#pragma unroll 1
        for (int kt = 0; kt < 8; kt++) {
            if (kt < 7) CP_WAIT1(); else CP_WAIT0();
            __syncthreads();                       // slab kt ready

            uint32_t ah[4], bq[2][4], bk[2][4];
            uint32_t aoff = (uint32_t)((wm * 16 + lrow) * 272
                                       + kt * 32 + lhalf * 16);
            LDM4(ah, sb + aoff);                   // x-hi only
            uint32_t pq = sb + F_W + (kt & 1) * 9216 + (wn >> 1) * 2304;
            uint32_t pk = pq + 4608;               // chunks 2,3
#pragma unroll
            for (int nt = 0; nt < 2; nt++) {
                uint32_t boff = (uint32_t)(lrow * 144
                                + ((wn & 1) * 32 + nt * 16) * 2 + lhalf * 16);
                LDM4T(bq[nt], pq + boff);
                LDM4T(bk[nt], pk + boff);
            }
#pragma unroll
            for (int j = 0; j < 4; j++)
                MMA_BF16(aq[j], ah, bq[j >> 1][2 * (j & 1)],
                         bq[j >> 1][2 * (j & 1) + 1]);
#pragma unroll
            for (int j = 0; j < 4; j++)
                MMA_BF16(ak[j], ah, bk[j >> 1][2 * (j & 1)],
                         bk[j >> 1][2 * (j & 1) + 1]);

            __syncthreads();                       // slot drained
            if (kt < 6) issue_qk2(sb, kt & 1, kt + 2, t);
        }
        // pre-issue out-proj slabs (ring2)
        issue_vo(sb, 0, 0, t, 6);
        issue_vo(sb, 1, 1, t, 6);

        // epilogue: q -> XL, k -> KB (single bf16)
        const int r0 = wm * 16 + qrow, r1 = r0 + 8;
#pragma unroll
        for (int j = 0; j < 4; j++) {
            int cb = (wn * 32 + j * 8 + qt2) * 2;
            *(uint32_t*)(smc + S_XL + r0 * 272 + cb) = packbf(aq[j][0], aq[j][1]);
            *(uint32_t*)(smc + S_XL + r1 * 272 + cb) = packbf(aq[j][2], aq[j][3]);
            *(uint32_t*)(smc + S_KB + r0 * 272 + cb) = packbf(ak[j][0], ak[j][1]);
            *(uint32_t*)(smc + S_KB + r1 * 272 + cb) = packbf(ak[j][2], ak[j][3]);
        }
    }
    __syncthreads();                 // Q/K/V visible

    // ================= attention: 1 task per warp =================
    {
        const int h  = w >> 2;
        const int i0 = (w & 3) << 4;
        const uint32_t QB = sb + S_XL;
        const uint32_t KBa = sb + S_KB;
        const uint32_t VB = sb + S_VH;

        float sc[7][4];
#pragma unroll
        for (int nt = 0; nt < 7; nt++)
#pragma unroll
            for (int e = 0; e < 4; e++) sc[nt][e] = 0.f;

        // S = q k^T, single-pass
#pragma unroll
        for (int kt = 0; kt < 2; kt++) {
            uint32_t ah[4], bh[4][4];
            uint32_t coff = (uint32_t)((h * 32 + kt * 16) * 2 + lhalf * 16);
            LDM4(ah, QB + (uint32_t)((i0 + lrow) * 272) + coff);
#pragma unroll
            for (int g = 0; g < 4; g++)
                LDM4(bh[g], KBa + (uint32_t)((g * 16 + lrow) * 272) + coff);
#pragma unroll
            for (int nt = 0; nt < 7; nt++)
                MMA_BF16(sc[nt], ah, bh[nt >> 1][nt & 1], bh[nt >> 1][2 + (nt & 1)]);
        }

        // softmax in fragments (unnormalized)
        const int r0 = i0 + qrow, r1 = r0 + 8;
        const int gi0 = r0 / 7, gj0 = r0 - 7 * gi0;
        const int gi1 = r1 / 7, gj1 = r1 - 7 * gi1;
        float rs0 = 0.f, rs1 = 0.f;
#pragma unroll
        for (int nt = 0; nt < 7; nt++) {
#pragma unroll
            for (int e = 0; e < 4; e++) {
                int j = nt * 8 + qt2 + (e & 1);
                int r = (e < 2) ? r0 : r1;
                float ev = 0.f;
                if (r < 49 && j < 49) {
                    int gj2 = j / 7;
                    int gjj = j - 7 * gj2;
                    int gi = (e < 2) ? gi0 : gi1;
                    int gj = (e < 2) ? gj0 : gj1;
                    int bidx = ((gi - gj2 + 6) * 13 + (gj - gjj + 6)) * 4 + h;
                    ev = __expf(sc[nt][e] * SCALE + bias_s[bidx]);
                }
                sc[nt][e] = ev;
                if (e < 2) rs0 += ev; else rs1 += ev;
            }
        }
        rs0 += __shfl_xor_sync(0xFFFFFFFFu, rs0, 1);
        rs0 += __shfl_xor_sync(0xFFFFFFFFu, rs0, 2);
        rs1 += __shfl_xor_sync(0xFFFFFFFFu, rs1, 1);
        rs1 += __shfl_xor_sync(0xFFFFFFFFu, rs1, 2);
        const float inv0 = (r0 < 49) ? 1.f / rs0 : 0.f;
        const float inv1 = (r1 < 49) ? 1.f / rs1 : 0.f;

        // O = P V (split P in-register x split V)
        float oc[4][4];
#pragma unroll
        for (int nt = 0; nt < 4; nt++)
#pragma unroll
            for (int e = 0; e < 4; e++) oc[nt][e] = 0.f;

#pragma unroll
        for (int kt2 = 0; kt2 < 4; kt2++) {
            const int lo = 2 * kt2, hi = lo + 1;
            float pe[8];
            pe[0] = sc[lo][0]; pe[1] = sc[lo][1];
            pe[2] = sc[lo][2]; pe[3] = sc[lo][3];
            if (hi < 7) {
                pe[4] = sc[hi][0]; pe[5] = sc[hi][1];
                pe[6] = sc[hi][2]; pe[7] = sc[hi][3];
            } else {
                pe[4] = pe[5] = pe[6] = pe[7] = 0.f;
            }
            uint32_t ph[4], pl[4];
#pragma unroll
            for (int g = 0; g < 4; g++) {
                float a = pe[2 * g], b = pe[2 * g + 1];
                uint32_t hp = packbf(a, b);
                float ra = a - __uint_as_float(hp << 16);
                float rb = b - __uint_as_float(hp & 0xFFFF0000u);
                ph[g] = hp;
                pl[g] = packbf(ra, rb);
            }
            uint32_t vh[2][4], vl[2][4];
#pragma unroll
            for (int g = 0; g < 2; g++) {
                uint32_t voff = (uint32_t)((kt2 * 16 + lrow) * 272
                                           + h * 64 + g * 32 + lhalf * 16);
                LDM4T(vh[g], VB + voff);
                LDM4T(vl[g], VB + 17408 + voff);
            }
#pragma unroll
            for (int nt = 0; nt < 4; nt++)
                MMA_BF16(oc[nt], ph, vh[nt >> 1][2 * (nt & 1)],
                         vh[nt >> 1][2 * (nt & 1) + 1]);
#pragma unroll
            for (int nt = 0; nt < 4; nt++)
                MMA_BF16(oc[nt], ph, vl[nt >> 1][2 * (nt & 1)],
                         vl[nt >> 1][2 * (nt & 1) + 1]);
#pragma unroll
            for (int nt = 0; nt < 4; nt++)
                MMA_BF16(oc[nt], pl, vh[nt >> 1][2 * (nt & 1)],
                         vh[nt >> 1][2 * (nt & 1) + 1]);
        }

        __syncthreads();   // all Q/K reads done before attn-out overwrites

        // attn-out: hi -> XH, lo -> KB (split bf16)
#pragma unroll
        for (int nt = 0; nt < 4; nt++) {
            int cb = (h * 32 + nt * 8 + qt2) * 2;
            if (r0 < 49) {
                float a = oc[nt][0] * inv0, b = oc[nt][1] * inv0;
                uint32_t hp = packbf(a, b);
                float ra = a - __uint_as_float(hp << 16);
                float rb = b - __uint_as_float(hp & 0xFFFF0000u);
                int off = r0 * 272 + cb;
                *(uint32_t*)(smc + off) = hp;
                *(uint32_t*)(smc + S_KB + off) = packbf(ra, rb);
            }
            if (r1 < 49) {
                float a = oc[nt][2] * inv1, b = oc[nt][3] * inv1;
                uint32_t hp = packbf(a, b);
                float ra = a - __uint_as_float(hp << 16);
                float rb = b - __uint_as_float(hp & 0xFFFF0000u);
                int off = r1 * 272 + cb;
                *(uint32_t*)(smc + off) = hp;
                *(uint32_t*)(smc + S_KB + off) = packbf(ra, rb);
            }
        }
        // note: rows 49..63 of XH keep x-hi pads (0); KB rows 49..63 keep
        // k pads (0) -> out-proj A pads are zero.
    }

    // ================= out-proj (3-pass split), ring2 =================
    {
        float acc[4][4];
#pragma unroll
        for (int j = 0; j < 4; j++)
#pragma unroll
            for (int e = 0; e < 4; e++) acc[j][e] = 0.f;

#pragma unroll 1
        for (int kt = 0; kt < 8; kt++) {
            if (kt < 7) CP_WAIT1(); else CP_WAIT0();
            __syncthreads();                   // slab ready + attn-out visible

            uint32_t ah[4], al[4], bh[2][4], bl[2][4];
            uint32_t aoff = (uint32_t)((wm * 16 + lrow) * 272
                                       + kt * 32 + lhalf * 16);
            LDM4(ah, sb + aoff);               // attn-out hi (XH)
            LDM4(al, sb + S_KB + aoff);        // attn-out lo (KB)
            uint32_t pbase = sb + F_W + (kt & 1) * 9216 + (wn >> 1) * 4608;
#pragma unroll
            for (int nt = 0; nt < 2; nt++) {
                uint32_t boff = (uint32_t)(lrow * 144
                                + ((wn & 1) * 32 + nt * 16) * 2 + lhalf * 16);
                LDM4T(bh[nt], pbase + boff);
                LDM4T(bl[nt], pbase + 2304 + boff);
            }
#pragma unroll
            for (int j = 0; j < 4; j++)
                MMA_BF16(acc[j], ah, bh[j >> 1][2 * (j & 1)],
                         bh[j >> 1][2 * (j & 1) + 1]);
#pragma unroll
            for (int j = 0; j < 4; j++)
                MMA_BF16(acc[j], ah, bl[j >> 1][2 * (j & 1)],
                         bl[j >> 1][2 * (j & 1) + 1]);
#pragma unroll
            for (int j = 0; j < 4; j++)
                MMA_BF16(acc[j], al, bh[j >> 1][2 * (j & 1)],
                         bh[j >> 1][2 * (j & 1) + 1]);

            __syncthreads();                   // slot drained
            if (kt < 6) issue_vo(sb, kt & 1, kt + 2, t, 6);
        }

        const int r0 = wm * 16 + qrow, r1 = r0 + 8;
#pragma unroll
        for (int j = 0; j < 4; j++) {
            int col = wn * 32 + j * 8 + qt2;
            if (r0 < 49)
                *(float2*)(out + (win * WN + r0) * (size_t)D + col) =
                    make_float2(acc[j][0], acc[j][1]);
            if (r1 < 49)
                *(float2*)(out + (win * WN + r1) * (size_t)D + col) =
                    make_float2(acc[j][2], acc[j][3]);
        }
    }
}

// ============================== launcher ==============================
extern "C" void kernel_launch(void* const* d_in, const int* in_sizes, int n_in,
                              void* d_out, int out_size) {
    const float* x    = (const float*)d_in[0];
    const float* wqkv = (const float*)d_in[1];
    const float* wout = (const float*)d_in[2];
    const float* btab = (const float*)d_in[3];
    float* out = (float*)d_out;

    const int n_win = in_sizes[0] / (WN * D);

    cudaFuncSetAttribute(fused1,
                         cudaFuncAttributeMaxDynamicSharedMemorySize, F_TOTAL);

    prepack_w<<<256, 256>>>(wqkv, wout);
    fused1<<<n_win, 512, F_TOTAL>>>(x, btab, out);
}

// round 17
// speedup vs baseline: 1.1092x; 1.0525x over previous
#include <cuda_runtime.h>
#include <cstdint>

// ============================ helpers ============================
__device__ __forceinline__ uint32_t smem_u32(const void* p) {
    uint32_t a;
    asm("{ .reg .u64 t; cvta.to.shared.u64 t, %1; cvt.u32.u64 %0, t; }" : "=r"(a) : "l"(p));
    return a;
}
__device__ __forceinline__ unsigned short f2bf(float f) {
    unsigned short r; asm("cvt.rn.bf16.f32 %0, %1;" : "=h"(r) : "f"(f)); return r;
}
__device__ __forceinline__ float bf2f(unsigned short u) {
    return __uint_as_float(((uint32_t)u) << 16);
}
__device__ __forceinline__ uint32_t packbf(float a, float b) {
    uint32_t r; asm("cvt.rn.bf16x2.f32 %0, %1, %2;" : "=r"(r) : "f"(b), "f"(a)); return r;
}

#define LDM4(r, addr) \
    asm volatile("ldmatrix.sync.aligned.m8n8.x4.shared.b16 {%0,%1,%2,%3}, [%4];" \
        : "=r"((r)[0]), "=r"((r)[1]), "=r"((r)[2]), "=r"((r)[3]) : "r"(addr))

#define LDM4T(r, addr) \
    asm volatile("ldmatrix.sync.aligned.m8n8.x4.trans.shared.b16 {%0,%1,%2,%3}, [%4];" \
        : "=r"((r)[0]), "=r"((r)[1]), "=r"((r)[2]), "=r"((r)[3]) : "r"(addr))

#define MMA_BF16(c, a, b0, b1) \
    asm volatile("mma.sync.aligned.m16n8k16.row.col.f32.bf16.bf16.f32 " \
        "{%0,%1,%2,%3}, {%4,%5,%6,%7}, {%8,%9}, {%0,%1,%2,%3};" \
        : "+f"((c)[0]), "+f"((c)[1]), "+f"((c)[2]), "+f"((c)[3]) \
        : "r"((a)[0]), "r"((a)[1]), "r"((a)[2]), "r"((a)[3]), "r"(b0), "r"(b1))

#define CP_COMMIT() asm volatile("cp.async.commit_group;" ::: "memory")
#define CP_WAIT0()  asm volatile("cp.async.wait_group 0;" ::: "memory")
#define CP_WAIT1()  asm volatile("cp.async.wait_group 1;" ::: "memory")
#define BAR_ARRIVE() asm volatile("bar.arrive 1, 512;" ::: "memory")
#define BAR_SYNC1()  asm volatile("bar.sync 1, 512;" ::: "memory")
__device__ __forceinline__ void cp16(uint32_t dst_smem, const void* src) {
    asm volatile("cp.async.cg.shared.global [%0], [%1], 16;"
        :: "r"(dst_smem), "l"(__cvta_generic_to_global(src)) : "memory");
}

// ============================ constants ============================
constexpr int WN  = 49;
constexpr int D   = 128;
constexpr float SCALE = 0.17677669529663687f;

// prepacked weights: 8 chunks (6 qkv + 2 wout), each [hi 18432 | lo 18432]
// per half: k(0..127)*144 + n_local(0..63)*2
__device__ unsigned char g_wpk[8][36864];

// per-CTA smem (one window):
// XH(x-hi/attn-hi) 0 | XL(x-lo->Q) 17408 | KB(k->attn-lo) 34816 |
// VH 52224 | VL 69632 | W ring 87040 (18432) | bias 105472
constexpr int S_XL   = 17408;
constexpr int S_KB   = 34816;
constexpr int S_VH   = 52224;
constexpr int S_VL   = 69632;
constexpr int F_W    = 87040;
constexpr int F_BIAS = 105472;
constexpr int F_TOTAL = 108176;

// ======================= weight prepack kernel =======================
__global__ void prepack_w(const float* __restrict__ wqkv,
                          const float* __restrict__ wout)
{
    int idx = blockIdx.x * 256 + threadIdx.x;
    if (idx < 128 * 384) {
        int k = idx / 384, n = idx - (idx / 384) * 384;
        float v = wqkv[idx];
        unsigned short h = f2bf(v), l = f2bf(v - bf2f(h));
        int c = n >> 6, nn = n & 63;
        *(unsigned short*)(g_wpk[c] + k * 144 + nn * 2) = h;
        *(unsigned short*)(g_wpk[c] + 18432 + k * 144 + nn * 2) = l;
    } else if (idx < 128 * 384 + 128 * 128) {
        int i2 = idx - 128 * 384;
        int k = i2 >> 7, n = i2 & 127;
        float v = wout[i2];
        unsigned short h = f2bf(v), l = f2bf(v - bf2f(h));
        int c = 6 + (n >> 6), nn = n & 63;
        *(unsigned short*)(g_wpk[c] + k * 144 + nn * 2) = h;
        *(unsigned short*)(g_wpk[c] + 18432 + k * 144 + nn * 2) = l;
    }
}

// ===== slab issuers: WARP-0 ONLY (lane-strided), one commit per slab =====
// v / out slabs: 9216 B (2 chunks x hi/lo); ring2 slots {0,9216}
__device__ __forceinline__ void issue_vo_w0(uint32_t sb, int slot, int kt,
                                            int lane, int cbase) {
#pragma unroll
    for (int i = lane; i < 576; i += 32) {
        int b = i / 144, ii = i - b * 144;
        cp16(sb + F_W + slot * 9216 + b * 2304 + ii * 16,
             g_wpk[cbase + (b >> 1)] + (b & 1) * 18432 + kt * 2304 + ii * 16);
    }
    CP_COMMIT();
}
// combined q+k slab: chunks 0..3 hi-halves, 9216 B; ring2
__device__ __forceinline__ void issue_qk2_w0(uint32_t sb, int slot, int kt,
                                             int lane) {
#pragma unroll
    for (int i = lane; i < 576; i += 32) {
        int b = i / 144, ii = i - b * 144;
        cp16(sb + F_W + slot * 9216 + b * 2304 + ii * 16,
             g_wpk[b] + kt * 2304 + ii * 16);
    }
    CP_COMMIT();
}

// ================== fused kernel: 1 window / CTA, 2 CTAs / SM ==================
__global__ __launch_bounds__(512, 2)
void fused1(const float* __restrict__ x, const float* __restrict__ btab,
            float* __restrict__ out)
{
    extern __shared__ char smc[];
    const uint32_t sb = smem_u32(smc);
    const int t = threadIdx.x;
    const int w = t >> 5, lane = t & 31;
    const int wm = w & 3, wn = w >> 2;
    const int lrow = lane & 15, lhalf = lane >> 4;
    const int qrow = lane >> 2, qt2 = (lane & 3) << 1;
    const size_t win = blockIdx.x;
    float* bias_s = (float*)(smc + F_BIAS);

    // bootstrap v-slab ring (warp 0 only)
    if (w == 0) {
        issue_vo_w0(sb, 0, 0, lane, 4);
        issue_vo_w0(sb, 1, 1, lane, 4);
    }

    // zero ONLY x pad rows 49..63 of XH/XL (Q/K/V pads become 0 via GEMM)
    {
        uint4 z4 = make_uint4(0u, 0u, 0u, 0u);
        for (int i = t; i < 510; i += 512) {
            int buf = (i >= 255);
            int k = i - buf * 255;
            *((uint4*)(smc + buf * S_XL + 49 * 272) + k) = z4;
        }
    }
    for (int i = t; i < 676; i += 512) bias_s[i] = btab[i];

    // stage x -> split bf16 (XH/XL)
    {
        const float* xw = x + win * (size_t)(WN * D);
        for (int idx4 = t; idx4 < 1568; idx4 += 512) {
            int r  = idx4 >> 5;
            int c4 = (idx4 & 31) << 2;
            float4 v = *(const float4*)(xw + r * D + c4);
            float vv[4] = {v.x, v.y, v.z, v.w};
            unsigned short hh[4], ll[4];
#pragma unroll
            for (int e = 0; e < 4; e++) {
                hh[e] = f2bf(vv[e]); ll[e] = f2bf(vv[e] - bf2f(hh[e]));
            }
            int off = r * 272 + c4 * 2;
            *(uint2*)(smc + off) = make_uint2(
                (uint32_t)hh[0] | ((uint32_t)hh[1] << 16),
                (uint32_t)hh[2] | ((uint32_t)hh[3] << 16));
            *(uint2*)(smc + S_XL + off) = make_uint2(
                (uint32_t)ll[0] | ((uint32_t)ll[1] << 16),
                (uint32_t)ll[2] | ((uint32_t)ll[3] << 16));
        }
    }

    // ================= stage V (3-pass split), ring2 =================
    {
        float acc[4][4];
#pragma unroll
        for (int j = 0; j < 4; j++)
#pragma unroll
            for (int e = 0; e < 4; e++) acc[j][e] = 0.f;

#pragma unroll 1
        for (int kt = 0; kt < 8; kt++) {
            if (w == 0) { if (kt < 7) CP_WAIT1(); else CP_WAIT0(); }
            __syncthreads();                       // slab kt visible to all

            uint32_t ah[4], al[4], bh[2][4], bl[2][4];
            uint32_t aoff = (uint32_t)((wm * 16 + lrow) * 272
                                       + kt * 32 + lhalf * 16);
            LDM4(ah, sb + aoff);
            LDM4(al, sb + S_XL + aoff);
            uint32_t pbase = sb + F_W + (kt & 1) * 9216 + (wn >> 1) * 4608;
#pragma unroll
            for (int nt = 0; nt < 2; nt++) {
                uint32_t boff = (uint32_t)(lrow * 144
                                + ((wn & 1) * 32 + nt * 16) * 2 + lhalf * 16);
                LDM4T(bh[nt], pbase + boff);
                LDM4T(bl[nt], pbase + 2304 + boff);
            }
#pragma unroll
            for (int j = 0; j < 4; j++)
                MMA_BF16(acc[j], ah, bh[j >> 1][2 * (j & 1)],
                         bh[j >> 1][2 * (j & 1) + 1]);
#pragma unroll
            for (int j = 0; j < 4; j++)
                MMA_BF16(acc[j], ah, bl[j >> 1][2 * (j & 1)],
                         bl[j >> 1][2 * (j & 1) + 1]);
#pragma unroll
            for (int j = 0; j < 4; j++)
                MMA_BF16(acc[j], al, bh[j >> 1][2 * (j & 1)],
                         bh[j >> 1][2 * (j & 1) + 1]);

            // drain notification: non-blocking for warps 1..15
            if (w) { BAR_ARRIVE(); }
            else {
                BAR_SYNC1();                       // all warps done with slot
                if (kt < 6) issue_vo_w0(sb, kt & 1, kt + 2, lane, 4);
                else if (kt == 6) {                // pre-issue q+k slabs
                    issue_qk2_w0(sb, 0, 0, lane);  // into slot 0 (drained)
                }
                else {                             // kt == 7: slot 1 drained
                    issue_qk2_w0(sb, 1, 1, lane);
                }
            }
        }

        // epilogue: split v -> VH/VL
        const int r0 = wm * 16 + qrow, r1 = r0 + 8;
#pragma unroll
        for (int j = 0; j < 4; j++) {
            int cb = (wn * 32 + j * 8 + qt2) * 2;
            {
                int off = r0 * 272 + cb;
                uint32_t hp = packbf(acc[j][0], acc[j][1]);
                float ra = acc[j][0] - __uint_as_float(hp << 16);
                float rb = acc[j][1] - __uint_as_float(hp & 0xFFFF0000u);
                *(uint32_t*)(smc + S_VH + off) = hp;
                *(uint32_t*)(smc + S_VL + off) = packbf(ra, rb);
            }
            {
                int off = r1 * 272 + cb;
                uint32_t hp = packbf(acc[j][2], acc[j][3]);
                float ra = acc[j][2] - __uint_as_float(hp << 16);
                float rb = acc[j][3] - __uint_as_float(hp & 0xFFFF0000u);
                *(uint32_t*)(smc + S_VH + off) = hp;
                *(uint32_t*)(smc + S_VL + off) = packbf(ra, rb);
            }
        }
    }

    // ============ merged Q+K stage: single-pass bf16, shared A, ring2 ============
    {
        float aq[4][4], ak[4][4];
#pragma unroll
        for (int j = 0; j < 4; j++)
#pragma unroll
            for (int e = 0; e < 4; e++) { aq[j][e] = 0.f; ak[j][e] = 0.f; }

#pragma unroll 1
        for (int kt = 0; kt < 8; kt++) {
            if (w == 0) { if (kt < 7) CP_WAIT1(); else CP_WAIT0(); }
            __syncthreads();                       // slab kt visible

            uint32_t ah[4], bq[2][4], bk[2][4];
            uint32_t aoff = (uint32_t)((wm * 16 + lrow) * 272
                                       + kt * 32 + lhalf * 16);
            LDM4(ah, sb + aoff);                   // x-hi only
            uint32_t pq = sb + F_W + (kt & 1) * 9216 + (wn >> 1) * 2304;
            uint32_t pk = pq + 4608;               // chunks 2,3
#pragma unroll
            for (int nt = 0; nt < 2; nt++) {
                uint32_t boff = (uint32_t)(lrow * 144
                                + ((wn & 1) * 32 + nt * 16) * 2 + lhalf * 16);
                LDM4T(bq[nt], pq + boff);
                LDM4T(bk[nt], pk + boff);
            }
#pragma unroll
            for (int j = 0; j < 4; j++)
                MMA_BF16(aq[j], ah, bq[j >> 1][2 * (j & 1)],
                         bq[j >> 1][2 * (j & 1) + 1]);
#pragma unroll
            for (int j = 0; j < 4; j++)
                MMA_BF16(ak[j], ah, bk[j >> 1][2 * (j & 1)],
                         bk[j >> 1][2 * (j & 1) + 1]);

            if (w) { BAR_ARRIVE(); }
            else {
                BAR_SYNC1();
                if (kt < 6) issue_qk2_w0(sb, kt & 1, kt + 2, lane);
                else if (kt == 6) issue_vo_w0(sb, 0, 0, lane, 6);  // wout
                else              issue_vo_w0(sb, 1, 1, lane, 6);
            }
        }

        // epilogue: q -> XL, k -> KB (single bf16)
        const int r0 = wm * 16 + qrow, r1 = r0 + 8;
#pragma unroll
        for (int j = 0; j < 4; j++) {
            int cb = (wn * 32 + j * 8 + qt2) * 2;
            *(uint32_t*)(smc + S_XL + r0 * 272 + cb) = packbf(aq[j][0], aq[j][1]);
            *(uint32_t*)(smc + S_XL + r1 * 272 + cb) = packbf(aq[j][2], aq[j][3]);
            *(uint32_t*)(smc + S_KB + r0 * 272 + cb) = packbf(ak[j][0], ak[j][1]);
            *(uint32_t*)(smc + S_KB + r1 * 272 + cb) = packbf(ak[j][2], ak[j][3]);
        }
    }
    __syncthreads();                 // Q/K/V visible

    // ================= attention: 1 task per warp =================
    {
        const int h  = w >> 2;
        const int i0 = (w & 3) << 4;
        const uint32_t QB = sb + S_XL;
        const uint32_t KBa = sb + S_KB;
        const uint32_t VB = sb + S_VH;

        float sc[7][4];
#pragma unroll
        for (int nt = 0; nt < 7; nt++)
#pragma unroll
            for (int e = 0; e < 4; e++) sc[nt][e] = 0.f;

        // S = q k^T, single-pass
#pragma unroll
        for (int kt = 0; kt < 2; kt++) {
            uint32_t ah[4], bh[4][4];
            uint32_t coff = (uint32_t)((h * 32 + kt * 16) * 2 + lhalf * 16);
            LDM4(ah, QB + (uint32_t)((i0 + lrow) * 272) + coff);
#pragma unroll
            for (int g = 0; g < 4; g++)
                LDM4(bh[g], KBa + (uint32_t)((g * 16 + lrow) * 272) + coff);
#pragma unroll
            for (int nt = 0; nt < 7; nt++)
                MMA_BF16(sc[nt], ah, bh[nt >> 1][nt & 1], bh[nt >> 1][2 + (nt & 1)]);
        }

        // softmax in fragments (unnormalized)
        const int r0 = i0 + qrow, r1 = r0 + 8;
        const int gi0 = r0 / 7, gj0 = r0 - 7 * gi0;
        const int gi1 = r1 / 7, gj1 = r1 - 7 * gi1;
        float rs0 = 0.f, rs1 = 0.f;
#pragma unroll
        for (int nt = 0; nt < 7; nt++) {
#pragma unroll
            for (int e = 0; e < 4; e++) {
                int j = nt * 8 + qt2 + (e & 1);
                int r = (e < 2) ? r0 : r1;
                float ev = 0.f;
                if (r < 49 && j < 49) {
                    int gj2 = j / 7;
                    int gjj = j - 7 * gj2;
                    int gi = (e < 2) ? gi0 : gi1;
                    int gj = (e < 2) ? gj0 : gj1;
                    int bidx = ((gi - gj2 + 6) * 13 + (gj - gjj + 6)) * 4 + h;
                    ev = __expf(sc[nt][e] * SCALE + bias_s[bidx]);
                }
                sc[nt][e] = ev;
                if (e < 2) rs0 += ev; else rs1 += ev;
            }
        }
        rs0 += __shfl_xor_sync(0xFFFFFFFFu, rs0, 1);
        rs0 += __shfl_xor_sync(0xFFFFFFFFu, rs0, 2);
        rs1 += __shfl_xor_sync(0xFFFFFFFFu, rs1, 1);
        rs1 += __shfl_xor_sync(0xFFFFFFFFu, rs1, 2);
        const float inv0 = (r0 < 49) ? 1.f / rs0 : 0.f;
        const float inv1 = (r1 < 49) ? 1.f / rs1 : 0.f;

        // O = P V (split P in-register x split V)
        float oc[4][4];
#pragma unroll
        for (int nt = 0; nt < 4; nt++)
#pragma unroll
            for (int e = 0; e < 4; e++) oc[nt][e] = 0.f;

#pragma unroll
        for (int kt2 = 0; kt2 < 4; kt2++) {
            const int lo = 2 * kt2, hi = lo + 1;
            float pe[8];
            pe[0] = sc[lo][0]; pe[1] = sc[lo][1];
            pe[2] = sc[lo][2]; pe[3] = sc[lo][3];
            if (hi < 7) {
                pe[4] = sc[hi][0]; pe[5] = sc[hi][1];
                pe[6] = sc[hi][2]; pe[7] = sc[hi][3];
            } else {
                pe[4] = pe[5] = pe[6] = pe[7] = 0.f;
            }
            uint32_t ph[4], pl[4];
#pragma unroll
            for (int g = 0; g < 4; g++) {
                float a = pe[2 * g], b = pe[2 * g + 1];
                uint32_t hp = packbf(a, b);
                float ra = a - __uint_as_float(hp << 16);
                float rb = b - __uint_as_float(hp & 0xFFFF0000u);
                ph[g] = hp;
                pl[g] = packbf(ra, rb);
            }
            uint32_t vh[2][4], vl[2][4];
#pragma unroll
            for (int g = 0; g < 2; g++) {
                uint32_t voff = (uint32_t)((kt2 * 16 + lrow) * 272
                                           + h * 64 + g * 32 + lhalf * 16);
                LDM4T(vh[g], VB + voff);
                LDM4T(vl[g], VB + 17408 + voff);
            }
#pragma unroll
            for (int nt = 0; nt < 4; nt++)
                MMA_BF16(oc[nt], ph, vh[nt >> 1][2 * (nt & 1)],
                         vh[nt >> 1][2 * (nt & 1) + 1]);
#pragma unroll
            for (int nt = 0; nt < 4; nt++)
                MMA_BF16(oc[nt], ph, vl[nt >> 1][2 * (nt & 1)],
                         vl[nt >> 1][2 * (nt & 1) + 1]);
#pragma unroll
            for (int nt = 0; nt < 4; nt++)
                MMA_BF16(oc[nt], pl, vh[nt >> 1][2 * (nt & 1)],
                         vh[nt >> 1][2 * (nt & 1) + 1]);
        }

        __syncthreads();   // all Q/K reads done before attn-out overwrites

        // attn-out: hi -> XH, lo -> KB (split bf16)
#pragma unroll
        for (int nt = 0; nt < 4; nt++) {
            int cb = (h * 32 + nt * 8 + qt2) * 2;
            if (r0 < 49) {
                float a = oc[nt][0] * inv0, b = oc[nt][1] * inv0;
                uint32_t hp = packbf(a, b);
                float ra = a - __uint_as_float(hp << 16);
                float rb = b - __uint_as_float(hp & 0xFFFF0000u);
                int off = r0 * 272 + cb;
                *(uint32_t*)(smc + off) = hp;
                *(uint32_t*)(smc + S_KB + off) = packbf(ra, rb);
            }
            if (r1 < 49) {
                float a = oc[nt][2] * inv1, b = oc[nt][3] * inv1;
                uint32_t hp = packbf(a, b);
                float ra = a - __uint_as_float(hp << 16);
                float rb = b - __uint_as_float(hp & 0xFFFF0000u);
                int off = r1 * 272 + cb;
                *(uint32_t*)(smc + off) = hp;
                *(uint32_t*)(smc + S_KB + off) = packbf(ra, rb);
            }
        }
        // rows 49..63 of XH keep x-hi pads (0); KB rows 49..63 keep k pads (0)
    }

    // ================= out-proj (3-pass split), ring2 =================
    {
        float acc[4][4];
#pragma unroll
        for (int j = 0; j < 4; j++)
#pragma unroll
            for (int e = 0; e < 4; e++) acc[j][e] = 0.f;

#pragma unroll 1
        for (int kt = 0; kt < 8; kt++) {
            if (w == 0) { if (kt < 7) CP_WAIT1(); else CP_WAIT0(); }
            __syncthreads();                   // slab ready + attn-out visible

            uint32_t ah[4], al[4], bh[2][4], bl[2][4];
            uint32_t aoff = (uint32_t)((wm * 16 + lrow) * 272
                                       + kt * 32 + lhalf * 16);
            LDM4(ah, sb + aoff);               // attn-out hi (XH)
            LDM4(al, sb + S_KB + aoff);        // attn-out lo (KB)
            uint32_t pbase = sb + F_W + (kt & 1) * 9216 + (wn >> 1) * 4608;
#pragma unroll
            for (int nt = 0; nt < 2; nt++) {
                uint32_t boff = (uint32_t)(lrow * 144
                                + ((wn & 1) * 32 + nt * 16) * 2 + lhalf * 16);
                LDM4T(bh[nt], pbase + boff);
                LDM4T(bl[nt], pbase + 2304 + boff);
            }
#pragma unroll
            for (int j = 0; j < 4; j++)
                MMA_BF16(acc[j], ah, bh[j >> 1][2 * (j & 1)],
                         bh[j >> 1][2 * (j & 1) + 1]);
#pragma unroll
            for (int j = 0; j < 4; j++)
                MMA_BF16(acc[j], ah, bl[j >> 1][2 * (j & 1)],
                         bl[j >> 1][2 * (j & 1) + 1]);
#pragma unroll
            for (int j = 0; j < 4; j++)
                MMA_BF16(acc[j], al, bh[j >> 1][2 * (j & 1)],
                         bh[j >> 1][2 * (j & 1) + 1]);

            if (w) { BAR_ARRIVE(); }
            else {
                BAR_SYNC1();
                if (kt < 6) issue_vo_w0(sb, kt & 1, kt + 2, lane, 6);
            }
        }

        const int r0 = wm * 16 + qrow, r1 = r0 + 8;
#pragma unroll
        for (int j = 0; j < 4; j++) {
            int col = wn * 32 + j * 8 + qt2;
            if (r0 < 49)
                *(float2*)(out + (win * WN + r0) * (size_t)D + col) =
                    make_float2(acc[j][0], acc[j][1]);
            if (r1 < 49)
                *(float2*)(out + (win * WN + r1) * (size_t)D + col) =
                    make_float2(acc[j][2], acc[j][3]);
        }
    }
}

// ============================== launcher ==============================
extern "C" void kernel_launch(void* const* d_in, const int* in_sizes, int n_in,
                              void* d_out, int out_size) {
    const float* x    = (const float*)d_in[0];
    const float* wqkv = (const float*)d_in[1];
    const float* wout = (const float*)d_in[2];
    const float* btab = (const float*)d_in[3];
    float* out = (float*)d_out;

    const int n_win = in_sizes[0] / (WN * D);

    cudaFuncSetAttribute(fused1,
                         cudaFuncAttributeMaxDynamicSharedMemorySize, F_TOTAL);

    prepack_w<<<256, 256>>>(wqkv, wout);
    fused1<<<n_win, 512, F_TOTAL>>>(x, btab, out);
}